// round 16
// baseline (speedup 1.0000x reference)
#include <cuda_runtime.h>
#include <cuda_bf16.h>
#include <cstdint>

#define T_STEPS 4096
#define HID     1000
#define VOC     32000
#define G_CTAS  125
#define GM      4097
#define NBLKS   250
#define MBLKS   33
#define NCHUNK  48              // 3072 / 64
#define TILE_B  16384           // 128 rows * 128 bytes
#define SENT    0x7FC0DEADu     // NaN payload — tanh/h0 can never produce it

// ---------------- device scratch (allocation-free rule) ----------------
__device__ __align__(256)  float    g_xseq[T_STEPS * HID];
// write-once h buffer: step m, producer g, warp q -> g_hpad[m*4096 + g*32 + q]
__device__ __align__(256)  unsigned g_hpad[(size_t)GM * 4096];
__device__ __align__(1024) char     g_A2T[(size_t)MBLKS * NCHUNK * TILE_B];
__device__ __align__(1024) char     g_B2T[(size_t)NBLKS * NCHUNK * TILE_B];

__device__ __forceinline__ uint32_t smem_u32(const void* p) {
    uint32_t a;
    asm("{ .reg .u64 t; cvta.to.shared.u64 t, %1; cvt.u32.u64 %0, t; }" : "=r"(a) : "l"(p));
    return a;
}
#define SW128(off) ((off) ^ (((off) >> 3) & 0x70))

// STRONG relaxed-atomic load/store (defined under races, no ordering cost)
__device__ __forceinline__ unsigned ld_rlx(const unsigned* p) {
    unsigned v;
    asm volatile("ld.relaxed.gpu.u32 %0, [%1];" : "=r"(v) : "l"(p));
    return v;
}
__device__ __forceinline__ void st_rlx(unsigned* p, unsigned v) {
    asm volatile("st.relaxed.gpu.u32 [%0], %1;" :: "l"(p), "r"(v) : "memory");
}

#define BAR_SYNC(id, n)   asm volatile("bar.sync %0, %1;"   :: "r"(id), "r"(n) : "memory")
#define BAR_ARRIVE(id, n) asm volatile("bar.arrive %0, %1;" :: "r"(id), "r"(n) : "memory")

#define MBAR_INIT(a, c) asm volatile("mbarrier.init.shared.b64 [%0], %1;" :: "r"(a), "r"(c) : "memory")
#define MBAR_ARRIVE(a)  asm volatile("mbarrier.arrive.shared.b64 _, [%0];" :: "r"(a) : "memory")
#define MBAR_EXPECT_TX(a, n) asm volatile("mbarrier.arrive.expect_tx.shared.b64 _, [%0], %1;" :: "r"(a), "r"(n) : "memory")
#define MBAR_WAIT(a, ph) do {                                                    \
    uint32_t _m = (a), _p = (ph), _d;                                            \
    asm volatile("{\n\t.reg .pred p;\n\t"                                        \
        "mbarrier.try_wait.parity.acquire.cta.shared::cta.b64 p, [%1], %2;\n\t"  \
        "selp.b32 %0, 1, 0, p;\n\t}" : "=r"(_d) : "r"(_m), "r"(_p) : "memory");  \
    if (!_d) {                                                                   \
        asm volatile("{\n\t.reg .pred P1;\n\tWL_%=:\n\t"                         \
            "mbarrier.try_wait.parity.acquire.cta.shared::cta.b64 P1, [%0], %1, 0x989680;\n\t" \
            "@P1 bra.uni WD_%=;\n\tbra.uni WL_%=;\n\tWD_%=:\n\t}"                \
            :: "r"(_m), "r"(_p) : "memory");                                     \
    }                                                                            \
} while (0)

__device__ __forceinline__ void bulk_cp(uint32_t dst, const void* src,
                                        uint32_t bytes, uint32_t mbar) {
    asm volatile(
        "cp.async.bulk.shared::cta.global.mbarrier::complete_tx::bytes [%0], [%1], %2, [%3];"
        :: "r"(dst), "l"(src), "r"(bytes), "r"(mbar) : "memory");
}
__device__ __forceinline__ void ldsm_x4(uint32_t* r, uint32_t addr) {
    asm volatile("ldmatrix.sync.aligned.m8n8.x4.shared.b16 {%0,%1,%2,%3}, [%4];"
                 : "=r"(r[0]), "=r"(r[1]), "=r"(r[2]), "=r"(r[3]) : "r"(addr));
}
__device__ __forceinline__ void ldsm_x2(uint32_t* r, uint32_t addr) {
    asm volatile("ldmatrix.sync.aligned.m8n8.x2.shared.b16 {%0,%1}, [%2];"
                 : "=r"(r[0]), "=r"(r[1]) : "r"(addr));
}
__device__ __forceinline__ void mma_bf16(float* d, const uint32_t* a, const uint32_t* b) {
    asm volatile(
        "mma.sync.aligned.m16n8k16.row.col.f32.bf16.bf16.f32 "
        "{%0,%1,%2,%3}, {%4,%5,%6,%7}, {%8,%9}, {%0,%1,%2,%3};"
        : "+f"(d[0]), "+f"(d[1]), "+f"(d[2]), "+f"(d[3])
        : "r"(a[0]), "r"(a[1]), "r"(a[2]), "r"(a[3]), "r"(b[0]), "r"(b[1]));
}

// ---------------------------------------------------------------------------
// Kernel 0: prefill write-once buffer with sentinel (runs first, every replay)
// ---------------------------------------------------------------------------
__global__ void prefill_kernel() {
    size_t i = (size_t)blockIdx.x * blockDim.x + threadIdx.x;
    if (i < (size_t)GM * 1024)
        ((uint4*)g_hpad)[i] = make_uint4(SENT, SENT, SENT, SENT);
}

// ---------------------------------------------------------------------------
// Kernel 1: gather x_seq + write h0 into step-0 quarters
// ---------------------------------------------------------------------------
__global__ void gather_kernel(const int* __restrict__ tok,
                              const float* __restrict__ Wxh,
                              const float* __restrict__ h0) {
    int i = blockIdx.x * blockDim.x + threadIdx.x;
    if (i < T_STEPS * HID) {
        int t = i / HID;
        int h = i - t * HID;
        g_xseq[i] = __ldg(&Wxh[(long long)h * VOC + tok[t]]);
    }
    if (i < HID)
        g_hpad[(i >> 3) * 32 + (i & 7)] = __float_as_uint(h0[i]);
}

// ---------------------------------------------------------------------------
// Kernel 2: fp32 -> bf16 split of W_hy, tiled pre-swizzled (16B granules).
// ---------------------------------------------------------------------------
__global__ void convertB_kernel(const float* __restrict__ Why) {
    int i = blockIdx.x * blockDim.x + threadIdx.x;
    if (i >= NBLKS * NCHUNK * 1024) return;
    int tileId = i >> 10;
    int e = i & 1023;
    int r = e >> 3, cg = e & 7;
    int nblk = tileId / NCHUNK, chunk = tileId - nblk * NCHUNK;
    int kp = chunk * 64 + cg * 8;
    int term = kp >> 10, k = kp & 1023;
    int n = nblk * 128 + r;
    bool lo = (term == 1);
    float v[8];
    if (k < HID) {
        float4 u0 = *(const float4*)(Why + (size_t)n * HID + k);
        float4 u1 = *(const float4*)(Why + (size_t)n * HID + k + 4);
        v[0]=u0.x; v[1]=u0.y; v[2]=u0.z; v[3]=u0.w;
        v[4]=u1.x; v[5]=u1.y; v[6]=u1.z; v[7]=u1.w;
    } else {
#pragma unroll
        for (int j = 0; j < 8; j++) v[j] = 0.f;
    }
    uint32_t p[4];
#pragma unroll
    for (int j = 0; j < 4; j++) {
        float a = v[2*j], b = v[2*j+1];
        if (lo) {
            a -= __bfloat162float(__float2bfloat16(a));
            b -= __bfloat162float(__float2bfloat16(b));
        }
        __nv_bfloat162 h = __floats2bfloat162_rn(a, b);
        p[j] = *(uint32_t*)&h;
    }
    uint32_t off = SW128((uint32_t)(r * 128 + cg * 16));
    *(uint4*)(g_B2T + (size_t)tileId * TILE_B + off) = make_uint4(p[0], p[1], p[2], p[3]);
}

// ---------------------------------------------------------------------------
// Kernel 3: persistent RNN scan — warp-specialized with TWO ALTERNATING
// named barriers (phase-overrun-proof: a poller can only re-arrive barrier X
// after its producer published t+2, which transitively requires our compute
// to have passed barrier X's previous phase).
// Warps 0-7: compute (one row each). Warps 8-11: pollers (125 active).
// ---------------------------------------------------------------------------
__global__ __launch_bounds__(384, 1)
void scan_kernel(const float* __restrict__ Whh,
                 const float* __restrict__ Bh) {
    __shared__ float hs[2][1024];
    const int tid  = threadIdx.x;
    const int wid  = tid >> 5;
    const int lane = tid & 31;
    const int g    = blockIdx.x;

    if (tid < 24) { hs[0][1000 + tid] = 0.f; hs[1][1000 + tid] = 0.f; }
    __syncthreads();   // single convergent sync: pads visible to everyone

    if (wid < 8) {
        // ===================== compute warps =====================
        const int row = g * 8 + wid;
        float w[8][4];
#pragma unroll
        for (int j = 0; j < 8; j++)
#pragma unroll
            for (int q = 0; q < 4; q++) {
                int k = 4 * lane + q + 128 * j;
                w[j][q] = (k < HID) ? __ldg(&Whh[row * HID + k]) : 0.0f;
            }
        const float bias = __ldg(&Bh[row]);

        for (int t = 0; t < T_STEPS; t++) {
            float xv = 0.0f;
            if (lane == 0) xv = __ldg(&g_xseq[t * HID + row]);  // hidden by barrier wait

            BAR_SYNC(1 + (t & 1), 384);   // wait for pollers to deliver hs[t&1]

            const float4* hb = (const float4*)hs[t & 1];
            float a0 = 0.f, a1 = 0.f, a2 = 0.f, a3 = 0.f;
#pragma unroll
            for (int j = 0; j < 8; j++) {
                float4 hv = hb[lane + 32 * j];
                a0 = fmaf(w[j][0], hv.x, a0);
                a1 = fmaf(w[j][1], hv.y, a1);
                a2 = fmaf(w[j][2], hv.z, a2);
                a3 = fmaf(w[j][3], hv.w, a3);
            }
            float acc = (a0 + a1) + (a2 + a3);
#pragma unroll
            for (int s = 16; s > 0; s >>= 1)
                acc += __shfl_xor_sync(0xffffffffu, acc, s);

            if (lane == 0) {
                float y = tanhf(acc + xv + bias);
                st_rlx(g_hpad + (size_t)(t + 1) * 4096 + g * 32 + wid,
                       __float_as_uint(y));
            }
        }
    } else {
        // ===================== poller warps ======================
        const int ptid = tid - 256;                  // 0..127
        const int p    = (ptid < G_CTAS) ? ptid : 0; // extras poll producer 0 (read-only)
        const bool wr  = (ptid < G_CTAS);

        for (int t = 0; t < T_STEPS; t++) {
            const unsigned* q = g_hpad + (size_t)t * 4096 + p * 32;
            uint32_t v0, v1, v2, v3, v4, v5, v6, v7;
            bool ok;
            do {
                v0 = ld_rlx(q + 0); v1 = ld_rlx(q + 1);
                v2 = ld_rlx(q + 2); v3 = ld_rlx(q + 3);
                v4 = ld_rlx(q + 4); v5 = ld_rlx(q + 5);
                v6 = ld_rlx(q + 6); v7 = ld_rlx(q + 7);
                ok = (v0 != SENT) & (v1 != SENT) & (v2 != SENT) & (v3 != SENT) &
                     (v4 != SENT) & (v5 != SENT) & (v6 != SENT) & (v7 != SENT);
            } while (!ok);
            if (wr) {
                float* d = &hs[t & 1][ptid * 8];
                d[0] = __uint_as_float(v0); d[1] = __uint_as_float(v1);
                d[2] = __uint_as_float(v2); d[3] = __uint_as_float(v3);
                d[4] = __uint_as_float(v4); d[5] = __uint_as_float(v5);
                d[6] = __uint_as_float(v6); d[7] = __uint_as_float(v7);
            }
            BAR_ARRIVE(1 + (t & 1), 384);  // signal; immediately pre-spin on t+1
        }
    }
}

// ---------------------------------------------------------------------------
// Kernel 4: fp32 -> bf16 split of h history (reads g_hpad), tiled pre-swizzled.
//   A' terms: [Ah | Ah | Al]
// ---------------------------------------------------------------------------
__global__ void convertA_kernel() {
    int i = blockIdx.x * blockDim.x + threadIdx.x;
    if (i >= MBLKS * NCHUNK * 1024) return;
    int tileId = i >> 10;
    int e = i & 1023;
    int r = e >> 3, cg = e & 7;
    int mblk = tileId / NCHUNK, chunk = tileId - mblk * NCHUNK;
    int kp = chunk * 64 + cg * 8;
    int term = kp >> 10, k = kp & 1023;
    int m = mblk * 128 + r;
    bool valid = (m < GM) && (k < HID);
    float v[8];
    if (valid) {
        const float* src = (const float*)g_hpad + (size_t)m * 4096 + (k >> 3) * 32;
        float4 u0 = *(const float4*)src;
        float4 u1 = *(const float4*)(src + 4);
        v[0]=u0.x; v[1]=u0.y; v[2]=u0.z; v[3]=u0.w;
        v[4]=u1.x; v[5]=u1.y; v[6]=u1.z; v[7]=u1.w;
    } else {
#pragma unroll
        for (int j = 0; j < 8; j++) v[j] = 0.f;
    }
    bool lo = (term == 2);
    uint32_t p[4];
#pragma unroll
    for (int j = 0; j < 4; j++) {
        float a = v[2*j], b = v[2*j+1];
        if (lo) {
            a -= __bfloat162float(__float2bfloat16(a));
            b -= __bfloat162float(__float2bfloat16(b));
        }
        __nv_bfloat162 h = __floats2bfloat162_rn(a, b);
        p[j] = *(uint32_t*)&h;
    }
    uint32_t off = SW128((uint32_t)(r * 128 + cg * 16));
    *(uint4*)(g_A2T + (size_t)tileId * TILE_B + off) = make_uint4(p[0], p[1], p[2], p[3]);
}

// ---------------------------------------------------------------------------
// Kernel 5: HMMA GEMM fed by cp.async.bulk (proven config, tensor ~80%).
// ---------------------------------------------------------------------------
#define NSTAGE 4
#define STAGE_BYTES (2 * TILE_B)
#define GEMM_SMEM (2048 + NSTAGE * STAGE_BYTES)

__global__ __launch_bounds__(256, 1)
void gemm_bulk_kernel(float* __restrict__ C) {
    extern __shared__ char dsm[];
    const uint32_t raw   = smem_u32(dsm);
    const uint32_t fullb = raw;
    const uint32_t emptb = raw + 64;
    const uint32_t tiles = (raw + 1024 + 1023) & ~1023u;

    const int tid  = threadIdx.x;
    const int wid  = tid >> 5;
    const int lane = tid & 31;
    const int wm   = wid >> 2;
    const int wn   = wid & 3;
    const int mblk = blockIdx.x;
    const int nblk = blockIdx.y;
    const int m0   = mblk * 128;
    const int n0   = nblk * 128;

    if (tid == 0) {
#pragma unroll
        for (int s = 0; s < NSTAGE; s++) {
            MBAR_INIT(fullb + 8 * s, 1);
            MBAR_INIT(emptb + 8 * s, 256);
        }
    }
    __syncthreads();

    const char* Abase = g_A2T + (size_t)mblk * NCHUNK * TILE_B;
    const char* Bbase = g_B2T + (size_t)nblk * NCHUNK * TILE_B;

    if (tid == 0) {
#pragma unroll
        for (int i = 0; i < NSTAGE; i++) {
            uint32_t mb = fullb + 8 * i;
            MBAR_EXPECT_TX(mb, STAGE_BYTES);
            bulk_cp(tiles + i * STAGE_BYTES,          Abase + (size_t)i * TILE_B, TILE_B, mb);
            bulk_cp(tiles + i * STAGE_BYTES + TILE_B, Bbase + (size_t)i * TILE_B, TILE_B, mb);
        }
    }

    float acc[4][4][4];
#pragma unroll
    for (int i = 0; i < 4; i++)
#pragma unroll
        for (int j = 0; j < 4; j++)
#pragma unroll
            for (int q = 0; q < 4; q++) acc[i][j][q] = 0.f;

    const uint32_t a_row = (uint32_t)(wm * 64 + (lane & 15));
    const uint32_t a_k   = (uint32_t)((lane >> 4) * 8);
    const uint32_t b_row = (uint32_t)(wn * 32 + (lane & 7));
    const uint32_t b_k   = (uint32_t)(((lane >> 3) & 1) * 8);

    for (int i = 0; i < NCHUNK; i++) {
        const int s = i & 3;
        MBAR_WAIT(fullb + 8 * s, (i >> 2) & 1);

        const uint32_t sA = tiles + s * STAGE_BYTES;
        const uint32_t sB = sA + TILE_B;
#pragma unroll
        for (int ks = 0; ks < 4; ks++) {
            uint32_t a[4][4], b[4][2];
#pragma unroll
            for (int fm = 0; fm < 4; fm++) {
                uint32_t off = (a_row + fm * 16) * 128 + (ks * 16 + a_k) * 2;
                ldsm_x4(a[fm], sA + SW128(off));
            }
#pragma unroll
            for (int fn = 0; fn < 4; fn++) {
                uint32_t off = (b_row + fn * 8) * 128 + (ks * 16 + b_k) * 2;
                ldsm_x2(b[fn], sB + SW128(off));
            }
#pragma unroll
            for (int fm = 0; fm < 4; fm++)
#pragma unroll
                for (int fn = 0; fn < 4; fn++)
                    mma_bf16(acc[fm][fn], a[fm], b[fn]);
        }
        MBAR_ARRIVE(emptb + 8 * s);

        if (tid == 0 && i + NSTAGE < NCHUNK) {
            MBAR_WAIT(emptb + 8 * s, (i >> 2) & 1);
            const int j = i + NSTAGE;
            uint32_t mb = fullb + 8 * s;
            MBAR_EXPECT_TX(mb, STAGE_BYTES);
            bulk_cp(tiles + s * STAGE_BYTES,          Abase + (size_t)j * TILE_B, TILE_B, mb);
            bulk_cp(tiles + s * STAGE_BYTES + TILE_B, Bbase + (size_t)j * TILE_B, TILE_B, mb);
        }
    }

    const int er = lane >> 2;
    const int ec = (lane & 3) * 2;
#pragma unroll
    for (int fm = 0; fm < 4; fm++) {
        int r0 = m0 + wm * 64 + fm * 16 + er;
#pragma unroll
        for (int fn = 0; fn < 4; fn++) {
            int c = n0 + wn * 32 + fn * 8 + ec;
            if (r0 < GM)
                *(float2*)(C + (size_t)r0 * VOC + c) = make_float2(acc[fm][fn][0], acc[fm][fn][1]);
            if (r0 + 8 < GM)
                *(float2*)(C + (size_t)(r0 + 8) * VOC + c) = make_float2(acc[fm][fn][2], acc[fm][fn][3]);
        }
    }
}

// ---------------------------------------------------------------------------
extern "C" void kernel_launch(void* const* d_in, const int* in_sizes, int n_in,
                              void* d_out, int out_size) {
    const int*   tok = (const int*)  d_in[0];
    const float* h0  = (const float*)d_in[1];
    const float* Wxh = (const float*)d_in[2];
    const float* Whh = (const float*)d_in[3];
    const float* Why = (const float*)d_in[4];
    const float* Bh  = (const float*)d_in[5];
    float* out = (float*)d_out;

    prefill_kernel<<<(int)(((size_t)GM * 1024 + 255) / 256), 256>>>();
    gather_kernel<<<(T_STEPS * HID + 255) / 256, 256>>>(tok, Wxh, h0);
    convertB_kernel<<<(NBLKS * NCHUNK * 1024 + 255) / 256, 256>>>(Why);
    scan_kernel<<<G_CTAS, 384>>>(Whh, Bh);
    convertA_kernel<<<(MBLKS * NCHUNK * 1024 + 255) / 256, 256>>>();

    cudaFuncSetAttribute(gemm_bulk_kernel,
                         cudaFuncAttributeMaxDynamicSharedMemorySize, GEMM_SMEM);
    dim3 ggrid(MBLKS, NBLKS);
    gemm_bulk_kernel<<<ggrid, 256, GEMM_SMEM>>>(out);
}

// round 17
// speedup vs baseline: 1.4783x; 1.4783x over previous
#include <cuda_runtime.h>
#include <cuda_bf16.h>
#include <cstdint>

#define T_STEPS 4096
#define HID     1000
#define VOC     32000
#define G_CTAS  125
#define GM      4097
#define NBLKS   250             // 128-row B' tile-blocks (convert layout)
#define GNB     125             // GEMM grid.y (256-col tiles)
#define MBLKS   33
#define NCHUNK  48              // 3072 / 64
#define TILE_B  16384           // 128 rows * 128 bytes
#define SENT    0x7FC0DEADu     // NaN payload — tanh/h0 can never produce it

// ---------------- device scratch (allocation-free rule) ----------------
__device__ __align__(256)  float    g_xseq[T_STEPS * HID];
// write-once h buffer: step m, producer g, warp q -> g_hpad[m*4096 + g*32 + q]
__device__ __align__(256)  unsigned g_hpad[(size_t)GM * 4096];
__device__ __align__(1024) char     g_A2T[(size_t)MBLKS * NCHUNK * TILE_B];
__device__ __align__(1024) char     g_B2T[(size_t)NBLKS * NCHUNK * TILE_B];

__device__ __forceinline__ uint32_t smem_u32(const void* p) {
    uint32_t a;
    asm("{ .reg .u64 t; cvta.to.shared.u64 t, %1; cvt.u32.u64 %0, t; }" : "=r"(a) : "l"(p));
    return a;
}
#define SW128(off) ((off) ^ (((off) >> 3) & 0x70))

// STRONG relaxed-atomic load/store (defined under races, no ordering cost)
__device__ __forceinline__ unsigned ld_rlx(const unsigned* p) {
    unsigned v;
    asm volatile("ld.relaxed.gpu.u32 %0, [%1];" : "=r"(v) : "l"(p));
    return v;
}
__device__ __forceinline__ void st_rlx(unsigned* p, unsigned v) {
    asm volatile("st.relaxed.gpu.u32 [%0], %1;" :: "l"(p), "r"(v) : "memory");
}

#define MBAR_INIT(a, c) asm volatile("mbarrier.init.shared.b64 [%0], %1;" :: "r"(a), "r"(c) : "memory")
#define MBAR_ARRIVE(a)  asm volatile("mbarrier.arrive.shared.b64 _, [%0];" :: "r"(a) : "memory")
#define MBAR_EXPECT_TX(a, n) asm volatile("mbarrier.arrive.expect_tx.shared.b64 _, [%0], %1;" :: "r"(a), "r"(n) : "memory")
#define MBAR_WAIT(a, ph) do {                                                    \
    uint32_t _m = (a), _p = (ph), _d;                                            \
    asm volatile("{\n\t.reg .pred p;\n\t"                                        \
        "mbarrier.try_wait.parity.acquire.cta.shared::cta.b64 p, [%1], %2;\n\t"  \
        "selp.b32 %0, 1, 0, p;\n\t}" : "=r"(_d) : "r"(_m), "r"(_p) : "memory");  \
    if (!_d) {                                                                   \
        asm volatile("{\n\t.reg .pred P1;\n\tWL_%=:\n\t"                         \
            "mbarrier.try_wait.parity.acquire.cta.shared::cta.b64 P1, [%0], %1, 0x989680;\n\t" \
            "@P1 bra.uni WD_%=;\n\tbra.uni WL_%=;\n\tWD_%=:\n\t}"                \
            :: "r"(_m), "r"(_p) : "memory");                                     \
    }                                                                            \
} while (0)

__device__ __forceinline__ void bulk_cp(uint32_t dst, const void* src,
                                        uint32_t bytes, uint32_t mbar) {
    asm volatile(
        "cp.async.bulk.shared::cta.global.mbarrier::complete_tx::bytes [%0], [%1], %2, [%3];"
        :: "r"(dst), "l"(src), "r"(bytes), "r"(mbar) : "memory");
}
__device__ __forceinline__ void ldsm_x4(uint32_t* r, uint32_t addr) {
    asm volatile("ldmatrix.sync.aligned.m8n8.x4.shared.b16 {%0,%1,%2,%3}, [%4];"
                 : "=r"(r[0]), "=r"(r[1]), "=r"(r[2]), "=r"(r[3]) : "r"(addr));
}
__device__ __forceinline__ void ldsm_x2(uint32_t* r, uint32_t addr) {
    asm volatile("ldmatrix.sync.aligned.m8n8.x2.shared.b16 {%0,%1}, [%2];"
                 : "=r"(r[0]), "=r"(r[1]) : "r"(addr));
}
__device__ __forceinline__ void mma_bf16(float* d, const uint32_t* a, const uint32_t* b) {
    asm volatile(
        "mma.sync.aligned.m16n8k16.row.col.f32.bf16.bf16.f32 "
        "{%0,%1,%2,%3}, {%4,%5,%6,%7}, {%8,%9}, {%0,%1,%2,%3};"
        : "+f"(d[0]), "+f"(d[1]), "+f"(d[2]), "+f"(d[3])
        : "r"(a[0]), "r"(a[1]), "r"(a[2]), "r"(a[3]), "r"(b[0]), "r"(b[1]));
}

// ---------------------------------------------------------------------------
// Kernel 0: prefill ONLY the polled quarters with sentinel.
// Quarter (m, g): 8 words at g_hpad[m*4096 + g*32], g < 125.
// ---------------------------------------------------------------------------
__global__ void prefill_kernel() {
    int i = blockIdx.x * blockDim.x + threadIdx.x;      // one quarter per thread
    if (i >= GM * G_CTAS) return;
    int m = i / G_CTAS;
    int g = i - m * G_CTAS;
    uint4* q = (uint4*)(g_hpad + (size_t)m * 4096 + g * 32);
    q[0] = make_uint4(SENT, SENT, SENT, SENT);
    q[1] = make_uint4(SENT, SENT, SENT, SENT);
}

// ---------------------------------------------------------------------------
// Kernel 1: gather x_seq + write h0 into step-0 quarters
// ---------------------------------------------------------------------------
__global__ void gather_kernel(const int* __restrict__ tok,
                              const float* __restrict__ Wxh,
                              const float* __restrict__ h0) {
    int i = blockIdx.x * blockDim.x + threadIdx.x;
    if (i < T_STEPS * HID) {
        int t = i / HID;
        int h = i - t * HID;
        g_xseq[i] = __ldg(&Wxh[(long long)h * VOC + tok[t]]);
    }
    if (i < HID)
        g_hpad[(i >> 3) * 32 + (i & 7)] = __float_as_uint(h0[i]);
}

// ---------------------------------------------------------------------------
// Kernel 2: fp32 -> bf16 split of W_hy, tiled pre-swizzled (16B granules).
// ---------------------------------------------------------------------------
__global__ void convertB_kernel(const float* __restrict__ Why) {
    int i = blockIdx.x * blockDim.x + threadIdx.x;
    if (i >= NBLKS * NCHUNK * 1024) return;
    int tileId = i >> 10;
    int e = i & 1023;
    int r = e >> 3, cg = e & 7;
    int nblk = tileId / NCHUNK, chunk = tileId - nblk * NCHUNK;
    int kp = chunk * 64 + cg * 8;
    int term = kp >> 10, k = kp & 1023;
    int n = nblk * 128 + r;
    bool lo = (term == 1);
    float v[8];
    if (k < HID) {
        float4 u0 = *(const float4*)(Why + (size_t)n * HID + k);
        float4 u1 = *(const float4*)(Why + (size_t)n * HID + k + 4);
        v[0]=u0.x; v[1]=u0.y; v[2]=u0.z; v[3]=u0.w;
        v[4]=u1.x; v[5]=u1.y; v[6]=u1.z; v[7]=u1.w;
    } else {
#pragma unroll
        for (int j = 0; j < 8; j++) v[j] = 0.f;
    }
    uint32_t p[4];
#pragma unroll
    for (int j = 0; j < 4; j++) {
        float a = v[2*j], b = v[2*j+1];
        if (lo) {
            a -= __bfloat162float(__float2bfloat16(a));
            b -= __bfloat162float(__float2bfloat16(b));
        }
        __nv_bfloat162 h = __floats2bfloat162_rn(a, b);
        p[j] = *(uint32_t*)&h;
    }
    uint32_t off = SW128((uint32_t)(r * 128 + cg * 16));
    *(uint4*)(g_B2T + (size_t)tileId * TILE_B + off) = make_uint4(p[0], p[1], p[2], p[3]);
}

// ---------------------------------------------------------------------------
// Kernel 3: persistent RNN scan — R13 verbatim (best-known: write-once
// sentinel exchange, relaxed-atomic loads/stores, zero ordering machinery).
// ---------------------------------------------------------------------------
__global__ __launch_bounds__(256, 1)
void scan_kernel(const float* __restrict__ Whh,
                 const float* __restrict__ Bh) {
    __shared__ float hs[2][1024];
    const int tid  = threadIdx.x;
    const int warp = tid >> 5;
    const int lane = tid & 31;
    const int g    = blockIdx.x;
    const int row  = g * 8 + warp;

    float w[8][4];
#pragma unroll
    for (int j = 0; j < 8; j++)
#pragma unroll
        for (int q = 0; q < 4; q++) {
            int k = 4 * lane + q + 128 * j;
            w[j][q] = (k < HID) ? __ldg(&Whh[row * HID + k]) : 0.0f;
        }
    const float bias = __ldg(&Bh[row]);

    if (tid < 24) { hs[0][1000 + tid] = 0.f; hs[1][1000 + tid] = 0.f; }

    for (int t = 0; t < T_STEPS; t++) {
        const int buf = t & 1;
        float xv = 0.0f;
        if (lane == 0) xv = __ldg(&g_xseq[t * HID + row]);   // prefetch

        if (tid < G_CTAS) {
            const unsigned* q = g_hpad + (size_t)t * 4096 + tid * 32;
            uint32_t v0, v1, v2, v3, v4, v5, v6, v7;
            bool ok;
            do {
                v0 = ld_rlx(q + 0); v1 = ld_rlx(q + 1);
                v2 = ld_rlx(q + 2); v3 = ld_rlx(q + 3);
                v4 = ld_rlx(q + 4); v5 = ld_rlx(q + 5);
                v6 = ld_rlx(q + 6); v7 = ld_rlx(q + 7);
                ok = (v0 != SENT) & (v1 != SENT) & (v2 != SENT) & (v3 != SENT) &
                     (v4 != SENT) & (v5 != SENT) & (v6 != SENT) & (v7 != SENT);
            } while (!ok);
            float* d = &hs[buf][tid * 8];
            d[0] = __uint_as_float(v0); d[1] = __uint_as_float(v1);
            d[2] = __uint_as_float(v2); d[3] = __uint_as_float(v3);
            d[4] = __uint_as_float(v4); d[5] = __uint_as_float(v5);
            d[6] = __uint_as_float(v6); d[7] = __uint_as_float(v7);
        }
        __syncthreads();

        const float4* hb = (const float4*)hs[buf];
        float a0 = 0.f, a1 = 0.f, a2 = 0.f, a3 = 0.f;
#pragma unroll
        for (int j = 0; j < 8; j++) {
            float4 hv = hb[lane + 32 * j];
            a0 = fmaf(w[j][0], hv.x, a0);
            a1 = fmaf(w[j][1], hv.y, a1);
            a2 = fmaf(w[j][2], hv.z, a2);
            a3 = fmaf(w[j][3], hv.w, a3);
        }
        float acc = (a0 + a1) + (a2 + a3);
#pragma unroll
        for (int s = 16; s > 0; s >>= 1)
            acc += __shfl_xor_sync(0xffffffffu, acc, s);

        if (lane == 0) {
            float y = tanhf(acc + xv + bias);
            st_rlx(g_hpad + (size_t)(t + 1) * 4096 + g * 32 + warp,
                   __float_as_uint(y));
        }
    }
}

// ---------------------------------------------------------------------------
// Kernel 4: fp32 -> bf16 split of h history (reads g_hpad), tiled pre-swizzled.
// ---------------------------------------------------------------------------
__global__ void convertA_kernel() {
    int i = blockIdx.x * blockDim.x + threadIdx.x;
    if (i >= MBLKS * NCHUNK * 1024) return;
    int tileId = i >> 10;
    int e = i & 1023;
    int r = e >> 3, cg = e & 7;
    int mblk = tileId / NCHUNK, chunk = tileId - mblk * NCHUNK;
    int kp = chunk * 64 + cg * 8;
    int term = kp >> 10, k = kp & 1023;
    int m = mblk * 128 + r;
    bool valid = (m < GM) && (k < HID);
    float v[8];
    if (valid) {
        const float* src = (const float*)g_hpad + (size_t)m * 4096 + (k >> 3) * 32;
        float4 u0 = *(const float4*)src;
        float4 u1 = *(const float4*)(src + 4);
        v[0]=u0.x; v[1]=u0.y; v[2]=u0.z; v[3]=u0.w;
        v[4]=u1.x; v[5]=u1.y; v[6]=u1.z; v[7]=u1.w;
    } else {
#pragma unroll
        for (int j = 0; j < 8; j++) v[j] = 0.f;
    }
    bool lo = (term == 2);
    uint32_t p[4];
#pragma unroll
    for (int j = 0; j < 4; j++) {
        float a = v[2*j], b = v[2*j+1];
        if (lo) {
            a -= __bfloat162float(__float2bfloat16(a));
            b -= __bfloat162float(__float2bfloat16(b));
        }
        __nv_bfloat162 h = __floats2bfloat162_rn(a, b);
        p[j] = *(uint32_t*)&h;
    }
    uint32_t off = SW128((uint32_t)(r * 128 + cg * 16));
    *(uint4*)(g_A2T + (size_t)tileId * TILE_B + off) = make_uint4(p[0], p[1], p[2], p[3]);
}

// ---------------------------------------------------------------------------
// Kernel 5: HMMA GEMM, tile 128x256, 3-stage bulk-cp pipeline (48KB/stage),
// warp tile 64x64 (8 warps 2x2x... 2 rows x 4 cols of 64x64).
// ---------------------------------------------------------------------------
#define NSTAGE 3
#define STAGE_BYTES (3 * TILE_B)            // A 16KB + B0 16KB + B1 16KB
#define GEMM_SMEM (2048 + NSTAGE * STAGE_BYTES)

__global__ __launch_bounds__(256, 1)
void gemm_bulk_kernel(float* __restrict__ C) {
    extern __shared__ char dsm[];
    const uint32_t raw   = smem_u32(dsm);
    const uint32_t fullb = raw;
    const uint32_t emptb = raw + 64;
    const uint32_t tiles = (raw + 1024 + 1023) & ~1023u;

    const int tid  = threadIdx.x;
    const int wid  = tid >> 5;
    const int lane = tid & 31;
    const int wm   = wid >> 2;          // 0..1
    const int wn   = wid & 3;           // 0..3
    const int mblk = blockIdx.x;
    const int nblk = blockIdx.y;        // 0..124 (256-col tiles)
    const int m0   = mblk * 128;
    const int n0   = nblk * 256;

    if (tid == 0) {
#pragma unroll
        for (int s = 0; s < NSTAGE; s++) {
            MBAR_INIT(fullb + 8 * s, 1);
            MBAR_INIT(emptb + 8 * s, 256);
        }
    }
    __syncthreads();

    const char* Abase  = g_A2T + (size_t)mblk * NCHUNK * TILE_B;
    const char* Bbase0 = g_B2T + (size_t)(2 * nblk)     * NCHUNK * TILE_B;
    const char* Bbase1 = g_B2T + (size_t)(2 * nblk + 1) * NCHUNK * TILE_B;

    if (tid == 0) {
#pragma unroll
        for (int i = 0; i < NSTAGE; i++) {
            uint32_t mb = fullb + 8 * i;
            MBAR_EXPECT_TX(mb, STAGE_BYTES);
            bulk_cp(tiles + i * STAGE_BYTES,              Abase  + (size_t)i * TILE_B, TILE_B, mb);
            bulk_cp(tiles + i * STAGE_BYTES + TILE_B,     Bbase0 + (size_t)i * TILE_B, TILE_B, mb);
            bulk_cp(tiles + i * STAGE_BYTES + 2 * TILE_B, Bbase1 + (size_t)i * TILE_B, TILE_B, mb);
        }
    }

    float acc[4][8][4];
#pragma unroll
    for (int i = 0; i < 4; i++)
#pragma unroll
        for (int j = 0; j < 8; j++)
#pragma unroll
            for (int q = 0; q < 4; q++) acc[i][j][q] = 0.f;

    const uint32_t a_row = (uint32_t)(wm * 64 + (lane & 15));
    const uint32_t a_k   = (uint32_t)((lane >> 4) * 8);
    const uint32_t b_rbase = (uint32_t)(wn * 64 + (lane & 7));
    const uint32_t b_k   = (uint32_t)(((lane >> 3) & 1) * 8);

    int fs = 0, fph = 0;
    for (int i = 0; i < NCHUNK; i++) {
        MBAR_WAIT(fullb + 8 * fs, fph);

        const uint32_t sA = tiles + fs * STAGE_BYTES;
        const uint32_t sB = sA + TILE_B;       // two stacked 128-row tiles
#pragma unroll
        for (int ks = 0; ks < 4; ks++) {
            uint32_t a[4][4], b[8][2];
#pragma unroll
            for (int fm = 0; fm < 4; fm++) {
                uint32_t off = (a_row + fm * 16) * 128 + (ks * 16 + a_k) * 2;
                ldsm_x4(a[fm], sA + SW128(off));
            }
#pragma unroll
            for (int fn = 0; fn < 8; fn++) {
                uint32_t r = b_rbase + fn * 8;                 // 0..255
                uint32_t addr = sB + (r >> 7) * TILE_B
                              + SW128((r & 127) * 128 + (ks * 16 + b_k) * 2);
                ldsm_x2(b[fn], addr);
            }
#pragma unroll
            for (int fm = 0; fm < 4; fm++)
#pragma unroll
                for (int fn = 0; fn < 8; fn++)
                    mma_bf16(acc[fm][fn], a[fm], b[fn]);
        }
        MBAR_ARRIVE(emptb + 8 * fs);

        if (tid == 0 && i + NSTAGE < NCHUNK) {
            MBAR_WAIT(emptb + 8 * fs, fph);
            const int j = i + NSTAGE;
            uint32_t mb = fullb + 8 * fs;
            MBAR_EXPECT_TX(mb, STAGE_BYTES);
            bulk_cp(tiles + fs * STAGE_BYTES,              Abase  + (size_t)j * TILE_B, TILE_B, mb);
            bulk_cp(tiles + fs * STAGE_BYTES + TILE_B,     Bbase0 + (size_t)j * TILE_B, TILE_B, mb);
            bulk_cp(tiles + fs * STAGE_BYTES + 2 * TILE_B, Bbase1 + (size_t)j * TILE_B, TILE_B, mb);
        }
        if (++fs == NSTAGE) { fs = 0; fph ^= 1; }
    }

    const int er = lane >> 2;
    const int ec = (lane & 3) * 2;
#pragma unroll
    for (int fm = 0; fm < 4; fm++) {
        int r0 = m0 + wm * 64 + fm * 16 + er;
#pragma unroll
        for (int fn = 0; fn < 8; fn++) {
            int c = n0 + wn * 64 + fn * 8 + ec;
            if (r0 < GM)
                *(float2*)(C + (size_t)r0 * VOC + c) = make_float2(acc[fm][fn][0], acc[fm][fn][1]);
            if (r0 + 8 < GM)
                *(float2*)(C + (size_t)(r0 + 8) * VOC + c) = make_float2(acc[fm][fn][2], acc[fm][fn][3]);
        }
    }
}

// ---------------------------------------------------------------------------
extern "C" void kernel_launch(void* const* d_in, const int* in_sizes, int n_in,
                              void* d_out, int out_size) {
    const int*   tok = (const int*)  d_in[0];
    const float* h0  = (const float*)d_in[1];
    const float* Wxh = (const float*)d_in[2];
    const float* Whh = (const float*)d_in[3];
    const float* Why = (const float*)d_in[4];
    const float* Bh  = (const float*)d_in[5];
    float* out = (float*)d_out;

    prefill_kernel<<<(GM * G_CTAS + 255) / 256, 256>>>();
    gather_kernel<<<(T_STEPS * HID + 255) / 256, 256>>>(tok, Wxh, h0);
    convertB_kernel<<<(NBLKS * NCHUNK * 1024 + 255) / 256, 256>>>(Why);
    scan_kernel<<<G_CTAS, 256>>>(Whh, Bh);
    convertA_kernel<<<(MBLKS * NCHUNK * 1024 + 255) / 256, 256>>>();

    cudaFuncSetAttribute(gemm_bulk_kernel,
                         cudaFuncAttributeMaxDynamicSharedMemorySize, GEMM_SMEM);
    dim3 ggrid(MBLKS, GNB);   // 33 x 125, m fastest
    gemm_bulk_kernel<<<ggrid, 256, GEMM_SMEM>>>(out);
}